// round 9
// baseline (speedup 1.0000x reference)
#include <cuda_runtime.h>
#include <math.h>

// Problem dims
#define SQ  512     // sequence length
#define BB  64      // batch
#define HH  512     // hidden
#define G4  2048    // 4*HH (gates i,f,g,o)

// ---------------------------------------------------------------------------
// Device scratch (allocation-free rule: __device__ globals)
// ---------------------------------------------------------------------------
__device__ float g_gates[2u * SQ * BB * G4];          // precomputed x@Wih^T + b, per dir  (536 MB)
__device__ float g_x1[(size_t)SQ * BB * 1024];        // layer output [t][b][fwd|bwd]      (134 MB)
__device__ float g_h[2][2][BB][HH];                   // [buf][dir][b][u] double-buffered h
__device__ float g_c[2][BB][HH];                      // [dir][b][u] (block-exclusive)
__device__ unsigned g_bar_count = 0;
__device__ unsigned g_bar_gen   = 0;

__device__ __forceinline__ float sigm(float x) { return 1.0f / (1.0f + expf(-x)); }

// Sense-reversing grid barrier (blocks guaranteed resident: grid=128 <= 148 SMs, 1 blk/SM)
__device__ __forceinline__ void grid_barrier(unsigned nblk) {
    __syncthreads();
    if (threadIdx.x == 0) {
        __threadfence();                                   // publish this block's writes
        unsigned gen = ((volatile unsigned*)&g_bar_gen)[0]; // read BEFORE arriving
        unsigned prev = atomicAdd(&g_bar_count, 1u);
        if (prev == nblk - 1u) {
            ((volatile unsigned*)&g_bar_count)[0] = 0u;    // reset before release
            __threadfence();
            atomicAdd(&g_bar_gen, 1u);                     // release
        } else {
            while (((volatile unsigned*)&g_bar_gen)[0] == gen) { __nanosleep(64); }
        }
        __threadfence();
    }
    __syncthreads();
}

// ---------------------------------------------------------------------------
// Init: copy h0/c0 of one layer (both dirs) into state buffers (buf 0)
// ---------------------------------------------------------------------------
__global__ void init_state(const float* __restrict__ h0, const float* __restrict__ c0, int layer) {
    int i = blockIdx.x * blockDim.x + threadIdx.x;
    const int n = 2 * BB * HH;                  // 65536 floats (2 dirs)
    if (i < n) {
        ((float*)g_h)[i] = h0[(size_t)layer * n + i];   // g_h[0][...] occupies first n floats
        ((float*)g_c)[i] = c0[(size_t)layer * n + i];
    }
}

// ---------------------------------------------------------------------------
// Input-projection GEMM:  g_gates[dir][t][b][j] = bias[j] + sum_k A[r][k]*W[j][k]
//   r = t*64 + b; A layout: xmode=0 -> input_seq [b][t][k] (K=256)
//                           xmode=1 -> g_x1      [t][b][k] (K=1024, contiguous rows)
// Block 128x128, K-tile 16, 256 threads, 8x8 microtile.
// ---------------------------------------------------------------------------
__global__ __launch_bounds__(256) void gemm_in(
    const float* __restrict__ X,
    const float* __restrict__ Wf, const float* __restrict__ bf,
    const float* __restrict__ Wb, const float* __restrict__ bb,
    int K, int xmode)
{
    const int dir = blockIdx.z;
    const float* __restrict__ W    = dir ? Wb : Wf;
    const float* __restrict__ bias = dir ? bb : bf;
    const float* __restrict__ A    = xmode ? (const float*)g_x1 : X;
    float* __restrict__ out = g_gates + (size_t)dir * SQ * BB * G4;

    __shared__ float As[16][132];
    __shared__ float Bs[16][132];

    const int tid  = threadIdx.x;
    const int tx   = tid & 15;
    const int ty   = tid >> 4;
    const int row0 = blockIdx.y * 128;
    const int col0 = blockIdx.x * 128;

    float acc[8][8];
#pragma unroll
    for (int i = 0; i < 8; ++i)
#pragma unroll
        for (int j = 0; j < 8; ++j) acc[i][j] = 0.0f;

    for (int k0 = 0; k0 < K; k0 += 16) {
#pragma unroll
        for (int l = 0; l < 2; ++l) {
            int f  = tid + l * 256;          // 0..511
            int rr = f >> 2;                 // 0..127
            int c4 = f & 3;                  // 0..3 (float4 within the 16-wide k tile)
            // A tile
            {
                int r = row0 + rr;
                size_t abase = xmode ? (size_t)r * K
                                     : (size_t)(r & 63) * (512u * (size_t)K) + (size_t)(r >> 6) * K;
                float4 v = *(const float4*)(A + abase + k0 + c4 * 4);
                As[c4 * 4 + 0][rr] = v.x;
                As[c4 * 4 + 1][rr] = v.y;
                As[c4 * 4 + 2][rr] = v.z;
                As[c4 * 4 + 3][rr] = v.w;
            }
            // B tile (W rows contiguous in k)
            {
                int cc = rr;
                float4 w4 = *(const float4*)(W + (size_t)(col0 + cc) * K + k0 + c4 * 4);
                Bs[c4 * 4 + 0][cc] = w4.x;
                Bs[c4 * 4 + 1][cc] = w4.y;
                Bs[c4 * 4 + 2][cc] = w4.z;
                Bs[c4 * 4 + 3][cc] = w4.w;
            }
        }
        __syncthreads();
#pragma unroll
        for (int kk = 0; kk < 16; ++kk) {
            float a[8], b[8];
            *(float4*)&a[0] = *(const float4*)&As[kk][ty * 8];
            *(float4*)&a[4] = *(const float4*)&As[kk][ty * 8 + 4];
            *(float4*)&b[0] = *(const float4*)&Bs[kk][tx * 8];
            *(float4*)&b[4] = *(const float4*)&Bs[kk][tx * 8 + 4];
#pragma unroll
            for (int i = 0; i < 8; ++i)
#pragma unroll
                for (int j = 0; j < 8; ++j)
                    acc[i][j] = fmaf(a[i], b[j], acc[i][j]);
        }
        __syncthreads();
    }

    float br[8];
#pragma unroll
    for (int j = 0; j < 8; ++j) br[j] = bias[col0 + tx * 8 + j];
#pragma unroll
    for (int i = 0; i < 8; ++i) {
        float* op = out + (size_t)(row0 + ty * 8 + i) * G4 + col0 + tx * 8;
        float4 o0 = make_float4(acc[i][0] + br[0], acc[i][1] + br[1],
                                acc[i][2] + br[2], acc[i][3] + br[3]);
        float4 o1 = make_float4(acc[i][4] + br[4], acc[i][5] + br[5],
                                acc[i][6] + br[6], acc[i][7] + br[7]);
        *(float4*)(op)     = o0;
        *(float4*)(op + 4) = o1;
    }
}

// ---------------------------------------------------------------------------
// Persistent recurrent kernel (one layer, both directions).
// grid = 128 blocks: dir = blk>>6, u-slice of 8 hidden units = (blk&63)*8.
// smem: Ws[512][32] (this block's 32 Whh gate-rows, cached for all steps),
//       Hs[64][512] (h staged per step via __ldcg), Ps[64][33] (pre-acts).
// ---------------------------------------------------------------------------
#define REC_SMEM ((512*32 + 64*512 + 64*33) * 4)

__global__ __launch_bounds__(256, 1) void lstm_rec(
    const float* __restrict__ whh_f, const float* __restrict__ whh_b)
{
    extern __shared__ float sm[];
    float* Ws = sm;                   // [512][32]   k-major
    float* Hs = sm + 512 * 32;        // [64][512]
    float* Ps = Hs + 64 * 512;        // [64][33]

    const int tid  = threadIdx.x;
    const int d    = blockIdx.x >> 6;
    const int u0   = (blockIdx.x & 63) * 8;
    const int c    = tid & 31;        // column within block: gate = c>>3, uu = c&7
    const int s    = tid >> 5;        // warp id -> batch group (8 batches)
    const unsigned nblk = gridDim.x;
    const float* __restrict__ whh = d ? whh_b : whh_f;

    // Cache this block's Whh slice: column c -> gate row j
    for (int idx = tid; idx < 32 * 512; idx += 256) {
        int cc = idx >> 9;            // 0..31
        int k  = idx & 511;
        int j  = (cc >> 3) * 512 + u0 + (cc & 7);
        Ws[k * 32 + cc] = whh[(size_t)j * 512 + k];
    }
    __syncthreads();

    for (int step = 0; step < SQ; ++step) {
        const int t   = d ? (SQ - 1 - step) : step;   // time alignment (bwd scans reversed)
        const int buf = step & 1;

        // Stage full H[64][512] of this dir from L2 (cg: bypass incoherent L1)
        {
            const float4* hs4 = (const float4*)&g_h[buf][d][0][0];
            float4* Hd4 = (float4*)Hs;
#pragma unroll 8
            for (int i = 0; i < 32; ++i)
                Hd4[tid + i * 256] = __ldcg(hs4 + tid + i * 256);
        }
        __syncthreads();

        // GEMM: acc[r] = sum_k Hs[s*8+r][k] * Ws[k][c]
        float acc[8];
#pragma unroll
        for (int r = 0; r < 8; ++r) acc[r] = 0.0f;
#pragma unroll 2
        for (int k = 0; k < 512; k += 4) {
            const float w0 = Ws[(k + 0) * 32 + c];
            const float w1 = Ws[(k + 1) * 32 + c];
            const float w2 = Ws[(k + 2) * 32 + c];
            const float w3 = Ws[(k + 3) * 32 + c];
#pragma unroll
            for (int r = 0; r < 8; ++r) {
                const float4 h4 = *(const float4*)&Hs[(s * 8 + r) * 512 + k];
                acc[r] = fmaf(h4.x, w0, acc[r]);
                acc[r] = fmaf(h4.y, w1, acc[r]);
                acc[r] = fmaf(h4.z, w2, acc[r]);
                acc[r] = fmaf(h4.w, w3, acc[r]);
            }
        }
#pragma unroll
        for (int r = 0; r < 8; ++r) Ps[(s * 8 + r) * 33 + c] = acc[r];
        __syncthreads();

        // Pointwise gate update for this block's (b, u) slice
        const float* __restrict__ gbase = g_gates + ((size_t)d * SQ + t) * (BB * G4);
        float* __restrict__ hdst = &g_h[buf ^ 1][d][0][0];
#pragma unroll
        for (int e2 = 0; e2 < 2; ++e2) {
            const int e  = tid + e2 * 256;     // 0..511
            const int b  = e >> 3;
            const int uu = e & 7;
            const int u  = u0 + uu;
            const float pi = Ps[b * 33 + uu]      + gbase[(size_t)b * G4 + u];
            const float pf = Ps[b * 33 + 8 + uu]  + gbase[(size_t)b * G4 + 512 + u];
            const float pg = Ps[b * 33 + 16 + uu] + gbase[(size_t)b * G4 + 1024 + u];
            const float po = Ps[b * 33 + 24 + uu] + gbase[(size_t)b * G4 + 1536 + u];
            const float cprev = g_c[d][b][u];
            const float cn = sigm(pf) * cprev + sigm(pi) * tanhf(pg);
            const float hn = sigm(po) * tanhf(cn);
            g_c[d][b][u] = cn;
            hdst[b * 512 + u] = hn;
            g_x1[((size_t)t * BB + b) * 1024 + d * 512 + u] = hn;  // time-aligned output
        }
        grid_barrier(nblk);
    }
}

// ---------------------------------------------------------------------------
// Final FC on last time step: out[b][o] = fc_b[o] + x1[511][b][:] . fc_w[o][:]
// ---------------------------------------------------------------------------
__global__ void fc_kernel(const float* __restrict__ fc_w, const float* __restrict__ fc_b,
                          float* __restrict__ out)
{
    const int b    = blockIdx.x;
    const int w    = threadIdx.x >> 5;   // output index 0..7
    const int lane = threadIdx.x & 31;
    const float* __restrict__ x  = g_x1 + ((size_t)(SQ - 1) * BB + b) * 1024;
    const float* __restrict__ wr = fc_w + (size_t)w * 1024;
    float sum = 0.0f;
    for (int k = lane; k < 1024; k += 32) sum = fmaf(x[k], wr[k], sum);
#pragma unroll
    for (int o = 16; o; o >>= 1) sum += __shfl_down_sync(0xffffffffu, sum, o);
    if (lane == 0) out[b * 8 + w] = sum + fc_b[w];
}

// ---------------------------------------------------------------------------
// Launch: layer0 [init, input GEMM, recurrence] -> layer1 -> FC
// ---------------------------------------------------------------------------
extern "C" void kernel_launch(void* const* d_in, const int* in_sizes, int n_in,
                              void* d_out, int out_size)
{
    const float* input_seq = (const float*)d_in[0];
    const float* h0        = (const float*)d_in[1];
    const float* c0        = (const float*)d_in[2];
    const float* w_ih_0f   = (const float*)d_in[3];
    const float* w_hh_0f   = (const float*)d_in[4];
    const float* b_0f      = (const float*)d_in[5];
    const float* w_ih_0b   = (const float*)d_in[6];
    const float* w_hh_0b   = (const float*)d_in[7];
    const float* b_0b      = (const float*)d_in[8];
    const float* w_ih_1f   = (const float*)d_in[9];
    const float* w_hh_1f   = (const float*)d_in[10];
    const float* b_1f      = (const float*)d_in[11];
    const float* w_ih_1b   = (const float*)d_in[12];
    const float* w_hh_1b   = (const float*)d_in[13];
    const float* b_1b      = (const float*)d_in[14];
    const float* fc_w      = (const float*)d_in[15];
    const float* fc_b      = (const float*)d_in[16];
    (void)in_sizes; (void)n_in; (void)out_size;

    cudaFuncSetAttribute(lstm_rec, cudaFuncAttributeMaxDynamicSharedMemorySize, REC_SMEM);

    dim3 ggrid(16, 256, 2);   // 2048/128 cols, 32768/128 rows, 2 dirs

    // Layer 0
    init_state<<<64, 1024>>>(h0, c0, 0);
    gemm_in<<<ggrid, 256>>>(input_seq, w_ih_0f, b_0f, w_ih_0b, b_0b, 256, 0);
    lstm_rec<<<128, 256, REC_SMEM>>>(w_hh_0f, w_hh_0b);

    // Layer 1 (input = g_x1 from layer 0)
    init_state<<<64, 1024>>>(h0, c0, 1);
    gemm_in<<<ggrid, 256>>>(nullptr, w_ih_1f, b_1f, w_ih_1b, b_1b, 1024, 1);
    lstm_rec<<<128, 256, REC_SMEM>>>(w_hh_1f, w_hh_1b);

    // FC on last time step
    fc_kernel<<<64, 256>>>(fc_w, fc_b, (float*)d_out);
}

// round 10
// speedup vs baseline: 1.0009x; 1.0009x over previous
#include <cuda_runtime.h>
#include <math.h>

// Problem dims
#define SQ  512     // sequence length
#define BB  64      // batch
#define HH  512     // hidden
#define G4  2048    // 4*HH (gates i,f,g,o)

// ---------------------------------------------------------------------------
// Device scratch (allocation-free rule: __device__ globals)
// ---------------------------------------------------------------------------
__device__ float g_gates[2u * SQ * BB * G4];          // precomputed x@Wih^T + b, per dir  (536 MB)
__device__ float g_x1[(size_t)SQ * BB * 1024];        // layer output [t][b][fwd|bwd]      (134 MB)
__device__ float g_h[2][2][BB][HH];                   // [buf][dir][b][u] double-buffered h
__device__ float g_c[2][BB][HH];                      // [dir][b][u] (block-exclusive)
__device__ unsigned g_bar_count = 0;
__device__ unsigned g_bar_gen   = 0;

__device__ __forceinline__ float sigm(float x) { return 1.0f / (1.0f + expf(-x)); }

// Sense-reversing grid barrier (blocks guaranteed resident: grid=128 <= 148 SMs, 1 blk/SM)
__device__ __forceinline__ void grid_barrier(unsigned nblk) {
    __syncthreads();
    if (threadIdx.x == 0) {
        __threadfence();                                   // publish this block's writes
        unsigned gen = ((volatile unsigned*)&g_bar_gen)[0]; // read BEFORE arriving
        unsigned prev = atomicAdd(&g_bar_count, 1u);
        if (prev == nblk - 1u) {
            ((volatile unsigned*)&g_bar_count)[0] = 0u;    // reset before release
            __threadfence();
            atomicAdd(&g_bar_gen, 1u);                     // release
        } else {
            while (((volatile unsigned*)&g_bar_gen)[0] == gen) { __nanosleep(64); }
        }
        __threadfence();
    }
    __syncthreads();
}

// ---------------------------------------------------------------------------
// Init: copy h0/c0 of one layer (both dirs) into state buffers (buf 0)
// ---------------------------------------------------------------------------
__global__ void init_state(const float* __restrict__ h0, const float* __restrict__ c0, int layer) {
    int i = blockIdx.x * blockDim.x + threadIdx.x;
    const int n = 2 * BB * HH;                  // 65536 floats (2 dirs)
    if (i < n) {
        ((float*)g_h)[i] = h0[(size_t)layer * n + i];   // g_h[0][...] occupies first n floats
        ((float*)g_c)[i] = c0[(size_t)layer * n + i];
    }
}

// ---------------------------------------------------------------------------
// Input-projection GEMM:  g_gates[dir][t][b][j] = bias[j] + sum_k A[r][k]*W[j][k]
//   r = t*64 + b; A layout: xmode=0 -> input_seq [b][t][k] (K=256)
//                           xmode=1 -> g_x1      [t][b][k] (K=1024, contiguous rows)
// Block 128x128, K-tile 16, 256 threads, 8x8 microtile.
// ---------------------------------------------------------------------------
__global__ __launch_bounds__(256) void gemm_in(
    const float* __restrict__ X,
    const float* __restrict__ Wf, const float* __restrict__ bf,
    const float* __restrict__ Wb, const float* __restrict__ bb,
    int K, int xmode)
{
    const int dir = blockIdx.z;
    const float* __restrict__ W    = dir ? Wb : Wf;
    const float* __restrict__ bias = dir ? bb : bf;
    const float* __restrict__ A    = xmode ? (const float*)g_x1 : X;
    float* __restrict__ out = g_gates + (size_t)dir * SQ * BB * G4;

    __shared__ float As[16][132];
    __shared__ float Bs[16][132];

    const int tid  = threadIdx.x;
    const int tx   = tid & 15;
    const int ty   = tid >> 4;
    const int row0 = blockIdx.y * 128;
    const int col0 = blockIdx.x * 128;

    float acc[8][8];
#pragma unroll
    for (int i = 0; i < 8; ++i)
#pragma unroll
        for (int j = 0; j < 8; ++j) acc[i][j] = 0.0f;

    for (int k0 = 0; k0 < K; k0 += 16) {
#pragma unroll
        for (int l = 0; l < 2; ++l) {
            int f  = tid + l * 256;          // 0..511
            int rr = f >> 2;                 // 0..127
            int c4 = f & 3;                  // 0..3 (float4 within the 16-wide k tile)
            // A tile
            {
                int r = row0 + rr;
                size_t abase = xmode ? (size_t)r * K
                                     : (size_t)(r & 63) * (512u * (size_t)K) + (size_t)(r >> 6) * K;
                float4 v = *(const float4*)(A + abase + k0 + c4 * 4);
                As[c4 * 4 + 0][rr] = v.x;
                As[c4 * 4 + 1][rr] = v.y;
                As[c4 * 4 + 2][rr] = v.z;
                As[c4 * 4 + 3][rr] = v.w;
            }
            // B tile (W rows contiguous in k)
            {
                int cc = rr;
                float4 w4 = *(const float4*)(W + (size_t)(col0 + cc) * K + k0 + c4 * 4);
                Bs[c4 * 4 + 0][cc] = w4.x;
                Bs[c4 * 4 + 1][cc] = w4.y;
                Bs[c4 * 4 + 2][cc] = w4.z;
                Bs[c4 * 4 + 3][cc] = w4.w;
            }
        }
        __syncthreads();
#pragma unroll
        for (int kk = 0; kk < 16; ++kk) {
            float a[8], b[8];
            *(float4*)&a[0] = *(const float4*)&As[kk][ty * 8];
            *(float4*)&a[4] = *(const float4*)&As[kk][ty * 8 + 4];
            *(float4*)&b[0] = *(const float4*)&Bs[kk][tx * 8];
            *(float4*)&b[4] = *(const float4*)&Bs[kk][tx * 8 + 4];
#pragma unroll
            for (int i = 0; i < 8; ++i)
#pragma unroll
                for (int j = 0; j < 8; ++j)
                    acc[i][j] = fmaf(a[i], b[j], acc[i][j]);
        }
        __syncthreads();
    }

    float br[8];
#pragma unroll
    for (int j = 0; j < 8; ++j) br[j] = bias[col0 + tx * 8 + j];
#pragma unroll
    for (int i = 0; i < 8; ++i) {
        float* op = out + (size_t)(row0 + ty * 8 + i) * G4 + col0 + tx * 8;
        float4 o0 = make_float4(acc[i][0] + br[0], acc[i][1] + br[1],
                                acc[i][2] + br[2], acc[i][3] + br[3]);
        float4 o1 = make_float4(acc[i][4] + br[4], acc[i][5] + br[5],
                                acc[i][6] + br[6], acc[i][7] + br[7]);
        *(float4*)(op)     = o0;
        *(float4*)(op + 4) = o1;
    }
}

// ---------------------------------------------------------------------------
// Persistent recurrent kernel (one layer, both directions).
// grid = 128 blocks: dir = blk>>6, u-slice of 8 hidden units = (blk&63)*8.
// smem: Ws[512][32] (this block's 32 Whh gate-rows, cached for all steps),
//       Hs[64][512] (h staged per step via __ldcg), Ps[64][33] (pre-acts).
// ---------------------------------------------------------------------------
#define REC_SMEM ((512*32 + 64*512 + 64*33) * 4)

__global__ __launch_bounds__(256, 1) void lstm_rec(
    const float* __restrict__ whh_f, const float* __restrict__ whh_b)
{
    extern __shared__ float sm[];
    float* Ws = sm;                   // [512][32]   k-major
    float* Hs = sm + 512 * 32;        // [64][512]
    float* Ps = Hs + 64 * 512;        // [64][33]

    const int tid  = threadIdx.x;
    const int d    = blockIdx.x >> 6;
    const int u0   = (blockIdx.x & 63) * 8;
    const int c    = tid & 31;        // column within block: gate = c>>3, uu = c&7
    const int s    = tid >> 5;        // warp id -> batch group (8 batches)
    const unsigned nblk = gridDim.x;
    const float* __restrict__ whh = d ? whh_b : whh_f;

    // Cache this block's Whh slice: column c -> gate row j
    for (int idx = tid; idx < 32 * 512; idx += 256) {
        int cc = idx >> 9;            // 0..31
        int k  = idx & 511;
        int j  = (cc >> 3) * 512 + u0 + (cc & 7);
        Ws[k * 32 + cc] = whh[(size_t)j * 512 + k];
    }
    __syncthreads();

    for (int step = 0; step < SQ; ++step) {
        const int t   = d ? (SQ - 1 - step) : step;   // time alignment (bwd scans reversed)
        const int buf = step & 1;

        // Stage full H[64][512] of this dir from L2 (cg: bypass incoherent L1)
        {
            const float4* hs4 = (const float4*)&g_h[buf][d][0][0];
            float4* Hd4 = (float4*)Hs;
#pragma unroll 8
            for (int i = 0; i < 32; ++i)
                Hd4[tid + i * 256] = __ldcg(hs4 + tid + i * 256);
        }
        __syncthreads();

        // GEMM: acc[r] = sum_k Hs[s*8+r][k] * Ws[k][c]
        float acc[8];
#pragma unroll
        for (int r = 0; r < 8; ++r) acc[r] = 0.0f;
#pragma unroll 2
        for (int k = 0; k < 512; k += 4) {
            const float w0 = Ws[(k + 0) * 32 + c];
            const float w1 = Ws[(k + 1) * 32 + c];
            const float w2 = Ws[(k + 2) * 32 + c];
            const float w3 = Ws[(k + 3) * 32 + c];
#pragma unroll
            for (int r = 0; r < 8; ++r) {
                const float4 h4 = *(const float4*)&Hs[(s * 8 + r) * 512 + k];
                acc[r] = fmaf(h4.x, w0, acc[r]);
                acc[r] = fmaf(h4.y, w1, acc[r]);
                acc[r] = fmaf(h4.z, w2, acc[r]);
                acc[r] = fmaf(h4.w, w3, acc[r]);
            }
        }
#pragma unroll
        for (int r = 0; r < 8; ++r) Ps[(s * 8 + r) * 33 + c] = acc[r];
        __syncthreads();

        // Pointwise gate update for this block's (b, u) slice
        const float* __restrict__ gbase = g_gates + ((size_t)d * SQ + t) * (BB * G4);
        float* __restrict__ hdst = &g_h[buf ^ 1][d][0][0];
#pragma unroll
        for (int e2 = 0; e2 < 2; ++e2) {
            const int e  = tid + e2 * 256;     // 0..511
            const int b  = e >> 3;
            const int uu = e & 7;
            const int u  = u0 + uu;
            const float pi = Ps[b * 33 + uu]      + gbase[(size_t)b * G4 + u];
            const float pf = Ps[b * 33 + 8 + uu]  + gbase[(size_t)b * G4 + 512 + u];
            const float pg = Ps[b * 33 + 16 + uu] + gbase[(size_t)b * G4 + 1024 + u];
            const float po = Ps[b * 33 + 24 + uu] + gbase[(size_t)b * G4 + 1536 + u];
            const float cprev = g_c[d][b][u];
            const float cn = sigm(pf) * cprev + sigm(pi) * tanhf(pg);
            const float hn = sigm(po) * tanhf(cn);
            g_c[d][b][u] = cn;
            hdst[b * 512 + u] = hn;
            g_x1[((size_t)t * BB + b) * 1024 + d * 512 + u] = hn;  // time-aligned output
        }
        grid_barrier(nblk);
    }
}

// ---------------------------------------------------------------------------
// Final FC on last time step: out[b][o] = fc_b[o] + x1[511][b][:] . fc_w[o][:]
// ---------------------------------------------------------------------------
__global__ void fc_kernel(const float* __restrict__ fc_w, const float* __restrict__ fc_b,
                          float* __restrict__ out)
{
    const int b    = blockIdx.x;
    const int w    = threadIdx.x >> 5;   // output index 0..7
    const int lane = threadIdx.x & 31;
    const float* __restrict__ x  = g_x1 + ((size_t)(SQ - 1) * BB + b) * 1024;
    const float* __restrict__ wr = fc_w + (size_t)w * 1024;
    float sum = 0.0f;
    for (int k = lane; k < 1024; k += 32) sum = fmaf(x[k], wr[k], sum);
#pragma unroll
    for (int o = 16; o; o >>= 1) sum += __shfl_down_sync(0xffffffffu, sum, o);
    if (lane == 0) out[b * 8 + w] = sum + fc_b[w];
}

// ---------------------------------------------------------------------------
// Launch: layer0 [init, input GEMM, recurrence] -> layer1 -> FC
// ---------------------------------------------------------------------------
extern "C" void kernel_launch(void* const* d_in, const int* in_sizes, int n_in,
                              void* d_out, int out_size)
{
    const float* input_seq = (const float*)d_in[0];
    const float* h0        = (const float*)d_in[1];
    const float* c0        = (const float*)d_in[2];
    const float* w_ih_0f   = (const float*)d_in[3];
    const float* w_hh_0f   = (const float*)d_in[4];
    const float* b_0f      = (const float*)d_in[5];
    const float* w_ih_0b   = (const float*)d_in[6];
    const float* w_hh_0b   = (const float*)d_in[7];
    const float* b_0b      = (const float*)d_in[8];
    const float* w_ih_1f   = (const float*)d_in[9];
    const float* w_hh_1f   = (const float*)d_in[10];
    const float* b_1f      = (const float*)d_in[11];
    const float* w_ih_1b   = (const float*)d_in[12];
    const float* w_hh_1b   = (const float*)d_in[13];
    const float* b_1b      = (const float*)d_in[14];
    const float* fc_w      = (const float*)d_in[15];
    const float* fc_b      = (const float*)d_in[16];
    (void)in_sizes; (void)n_in; (void)out_size;

    cudaFuncSetAttribute(lstm_rec, cudaFuncAttributeMaxDynamicSharedMemorySize, REC_SMEM);

    dim3 ggrid(16, 256, 2);   // 2048/128 cols, 32768/128 rows, 2 dirs

    // Layer 0
    init_state<<<64, 1024>>>(h0, c0, 0);
    gemm_in<<<ggrid, 256>>>(input_seq, w_ih_0f, b_0f, w_ih_0b, b_0b, 256, 0);
    lstm_rec<<<128, 256, REC_SMEM>>>(w_hh_0f, w_hh_0b);

    // Layer 1 (input = g_x1 from layer 0)
    init_state<<<64, 1024>>>(h0, c0, 1);
    gemm_in<<<ggrid, 256>>>(nullptr, w_ih_1f, b_1f, w_ih_1b, b_1b, 1024, 1);
    lstm_rec<<<128, 256, REC_SMEM>>>(w_hh_1f, w_hh_1b);

    // FC on last time step
    fc_kernel<<<64, 256>>>(fc_w, fc_b, (float*)d_out);
}

// round 11
// speedup vs baseline: 2.1800x; 2.1780x over previous
#include <cuda_runtime.h>
#include <math.h>

// Problem dims
#define SQ  512     // sequence length
#define BB  64      // batch
#define HH  512     // hidden
#define G4  2048    // 4*HH (gates i,f,g,o)

// ---------------------------------------------------------------------------
// Device scratch (allocation-free rule: __device__ globals)
// ---------------------------------------------------------------------------
__device__ float g_gates[2u * SQ * BB * G4];          // x@Wih^T + b, per dir
__device__ float g_x1[(size_t)SQ * BB * 1024];        // layer output [t][b][fwd|bwd]
__device__ float g_h[2][2][BB][HH];                   // [buf][dir][b][u] double-buffered h
__device__ float g_c[2][BB][HH];                      // [dir][b][u] (block-exclusive)
__device__ unsigned g_bar_count = 0;
__device__ unsigned g_bar_gen   = 0;

__device__ __forceinline__ float sigm(float x) { return 1.0f / (1.0f + expf(-x)); }

__device__ __forceinline__ unsigned f2tf(float x) {
    unsigned u; asm("cvt.rna.tf32.f32 %0, %1;" : "=r"(u) : "f"(x)); return u;
}
__device__ __forceinline__ unsigned fu(float x) { return __float_as_uint(x); }

// mma.sync m16n8k8 tf32, fp32 accumulate, D = A*B + D
__device__ __forceinline__ void mma_tf32(float* c, const unsigned* a, const unsigned* b) {
    asm("mma.sync.aligned.m16n8k8.row.col.f32.tf32.tf32.f32 "
        "{%0,%1,%2,%3}, {%4,%5,%6,%7}, {%8,%9}, {%0,%1,%2,%3};"
        : "+f"(c[0]), "+f"(c[1]), "+f"(c[2]), "+f"(c[3])
        : "r"(a[0]), "r"(a[1]), "r"(a[2]), "r"(a[3]), "r"(b[0]), "r"(b[1]));
}

// Sense-reversing grid barrier (128 resident blocks, 1/SM)
__device__ __forceinline__ void grid_barrier(unsigned nblk) {
    __syncthreads();
    if (threadIdx.x == 0) {
        __threadfence();
        unsigned gen = ((volatile unsigned*)&g_bar_gen)[0];
        unsigned prev = atomicAdd(&g_bar_count, 1u);
        if (prev == nblk - 1u) {
            ((volatile unsigned*)&g_bar_count)[0] = 0u;
            __threadfence();
            atomicAdd(&g_bar_gen, 1u);
        } else {
            while (((volatile unsigned*)&g_bar_gen)[0] == gen) { __nanosleep(32); }
        }
        __threadfence();
    }
    __syncthreads();
}

// ---------------------------------------------------------------------------
// Init: copy h0/c0 of one layer (both dirs) into state buffers (buf 0)
// ---------------------------------------------------------------------------
__global__ void init_state(const float* __restrict__ h0, const float* __restrict__ c0, int layer) {
    int i = blockIdx.x * blockDim.x + threadIdx.x;
    const int n = 2 * BB * HH;
    if (i < n) {
        ((float*)g_h)[i] = h0[(size_t)layer * n + i];
        ((float*)g_c)[i] = c0[(size_t)layer * n + i];
    }
}

// ---------------------------------------------------------------------------
// Input-projection GEMM on tensor cores (tf32 mma.sync, fp32 accumulate)
//   out[r][j] = bias[j] + sum_k A[r][k] * W[j][k],  r = t*64+b  (M=32768, N=2048)
// Block tile 128x128, k-tile 32. 8 warps: warp w -> m-rows [(w>>1)*32,+32),
// n-cols [(w&1)*64,+64)  (2 m16-tiles x 8 n8-tiles per warp).
// ---------------------------------------------------------------------------
__global__ __launch_bounds__(256, 2) void gemm_tc(
    const float* __restrict__ X,
    const float* __restrict__ Wf, const float* __restrict__ bf,
    const float* __restrict__ Wb, const float* __restrict__ bb,
    int K, int xmode)
{
    const int dir = blockIdx.z;
    const float* __restrict__ W    = dir ? Wb : Wf;
    const float* __restrict__ bias = dir ? bb : bf;
    const float* __restrict__ A    = xmode ? (const float*)g_x1 : X;
    float* __restrict__ out = g_gates + (size_t)dir * SQ * BB * G4;

    __shared__ float As[128][36];   // tf32 bits, pad 36 -> (4m+k)%32 conflict-free frags
    __shared__ float Bs[128][36];

    const int tid  = threadIdx.x;
    const int w    = tid >> 5;
    const int lane = tid & 31;
    const int gp   = lane >> 2;     // group id (row part)
    const int tg   = lane & 3;      // thread-in-group (col part)
    const int mb   = (w >> 1) * 32; // warp m base within block
    const int nb   = (w & 1) * 64;  // warp n base within block
    const int row0 = blockIdx.y * 128;
    const int col0 = blockIdx.x * 128;

    float c0[8][4], c1[8][4];
#pragma unroll
    for (int ni = 0; ni < 8; ++ni)
#pragma unroll
        for (int q = 0; q < 4; ++q) { c0[ni][q] = 0.0f; c1[ni][q] = 0.0f; }

    for (int k0 = 0; k0 < K; k0 += 32) {
        // Stage A,B tiles (1024 float4 each), convert to tf32
#pragma unroll
        for (int l = 0; l < 4; ++l) {
            int f  = tid + l * 256;       // 0..1023
            int rr = f >> 3;              // 0..127
            int c4 = f & 7;               // 0..7
            {
                int r = row0 + rr;
                size_t abase = xmode ? (size_t)r * K
                                     : (size_t)(r & 63) * (512u * (size_t)K) + (size_t)(r >> 6) * K;
                float4 v = *(const float4*)(A + abase + k0 + c4 * 4);
                float4 cv;
                cv.x = __uint_as_float(f2tf(v.x)); cv.y = __uint_as_float(f2tf(v.y));
                cv.z = __uint_as_float(f2tf(v.z)); cv.w = __uint_as_float(f2tf(v.w));
                *(float4*)&As[rr][c4 * 4] = cv;
            }
            {
                float4 v = *(const float4*)(W + (size_t)(col0 + rr) * K + k0 + c4 * 4);
                float4 cv;
                cv.x = __uint_as_float(f2tf(v.x)); cv.y = __uint_as_float(f2tf(v.y));
                cv.z = __uint_as_float(f2tf(v.z)); cv.w = __uint_as_float(f2tf(v.w));
                *(float4*)&Bs[rr][c4 * 4] = cv;
            }
        }
        __syncthreads();

#pragma unroll
        for (int kk8 = 0; kk8 < 4; ++kk8) {
            const int kb = kk8 * 8;
            unsigned a0[4], a1[4];
            {
                int m = mb + gp;
                a0[0] = fu(As[m][kb + tg]);      a0[1] = fu(As[m + 8][kb + tg]);
                a0[2] = fu(As[m][kb + tg + 4]);  a0[3] = fu(As[m + 8][kb + tg + 4]);
                m = mb + 16 + gp;
                a1[0] = fu(As[m][kb + tg]);      a1[1] = fu(As[m + 8][kb + tg]);
                a1[2] = fu(As[m][kb + tg + 4]);  a1[3] = fu(As[m + 8][kb + tg + 4]);
            }
#pragma unroll
            for (int ni = 0; ni < 8; ++ni) {
                unsigned bf2[2];
                int n = nb + ni * 8 + gp;
                bf2[0] = fu(Bs[n][kb + tg]);
                bf2[1] = fu(Bs[n][kb + tg + 4]);
                mma_tf32(c0[ni], a0, bf2);
                mma_tf32(c1[ni], a1, bf2);
            }
        }
        __syncthreads();
    }

    // Epilogue: add bias, write fp32
#pragma unroll
    for (int ni = 0; ni < 8; ++ni) {
        const int col = col0 + nb + ni * 8 + 2 * tg;
        const float bx = bias[col], by = bias[col + 1];
#pragma unroll
        for (int mi = 0; mi < 2; ++mi) {
            float (*cc)[4] = mi ? c1 : c0;
            const int row = row0 + mb + mi * 16 + gp;
            float2 v0 = make_float2(cc[ni][0] + bx, cc[ni][1] + by);
            float2 v1 = make_float2(cc[ni][2] + bx, cc[ni][3] + by);
            *(float2*)(out + (size_t)row * G4 + col)       = v0;
            *(float2*)(out + (size_t)(row + 8) * G4 + col) = v1;
        }
    }
}

// ---------------------------------------------------------------------------
// Persistent recurrent kernel with tf32 mma (one layer, both directions).
// grid = 128 blocks: dir = blk>>6, u-slice of 8 hidden units = (blk&63)*8.
// Per step per block: Ps[64 b][32 c] = Hs[64][512] x Whh_slice[512][32]
//   (4 m16-tiles x 4 n8-tiles x 64 k8-steps). 8 warps: warp w -> mtile w>>1,
//   ntiles {2(w&1), 2(w&1)+1}.
// smem: Hs[64][516] (tf32 h, staged per step; stride 516 -> conflict-free frags)
//       Wp fragment-packed B (built once, float2 per lane, reused 512 steps)
//       Ps[64][34] fp32 pre-activations
// ---------------------------------------------------------------------------
#define HSTR 516
#define PSTR 34
#define REC_SMEM ((64*HSTR + 64*4*32*2 + 64*PSTR) * 4)

__global__ __launch_bounds__(256, 1) void lstm_rec_tc(
    const float* __restrict__ whh_f, const float* __restrict__ whh_b)
{
    extern __shared__ float sm[];
    float* Hs  = sm;                           // 64*516
    float* Wpf = sm + 64 * HSTR;               // 64*4*32 float2 = 16384 floats
    float* Ps  = Wpf + 64 * 4 * 32 * 2;        // 64*34

    const int tid  = threadIdx.x;
    const int w    = tid >> 5;
    const int lane = tid & 31;
    const int gp   = lane >> 2;
    const int tg   = lane & 3;
    const int d    = blockIdx.x >> 6;
    const int u0   = (blockIdx.x & 63) * 8;
    const unsigned nblk = gridDim.x;
    const float* __restrict__ whh = d ? whh_b : whh_f;

    const int m0     = (w >> 1) * 16;          // warp's m16 tile base (batch rows)
    const int nhalf  = (w & 1);                // ntiles {2*nhalf, 2*nhalf+1}

    // Build fragment-packed B once: Wp[kk][nt][lane] = {b0,b1} (tf32)
    //   b0 = W[kk*8 + tg][nt*8 + gp], b1 = W[kk*8+4+tg][nt*8+gp]
    //   W[k][c] = whh[(gate*512 + u0 + uu)*512 + k], gate = nt, uu = col-in-tile
    float2* Wp2 = (float2*)Wpf;
    for (int e = tid; e < 64 * 4 * 32; e += 256) {
        int el = e & 31, nt = (e >> 5) & 3, kk = e >> 7;
        int uu = el >> 2, tgg = el & 3;
        size_t jrow = (size_t)(nt * 512 + u0 + uu) * 512;
        int k = kk * 8 + tgg;
        float2 v;
        v.x = __uint_as_float(f2tf(whh[jrow + k]));
        v.y = __uint_as_float(f2tf(whh[jrow + k + 4]));
        Wp2[e] = v;
    }
    __syncthreads();

    for (int step = 0; step < SQ; ++step) {
        const int t   = d ? (SQ - 1 - step) : step;
        const int buf = step & 1;

        // Stage H[64][512] of this dir from L2 (cg), convert to tf32
        {
            const float4* hs4 = (const float4*)&g_h[buf][d][0][0];
#pragma unroll 8
            for (int i = 0; i < 32; ++i) {
                int f  = tid + i * 256;       // 0..8191 float4s
                int b  = f >> 7;
                int k4 = f & 127;
                float4 v = __ldcg(hs4 + f);
                float4 cv;
                cv.x = __uint_as_float(f2tf(v.x)); cv.y = __uint_as_float(f2tf(v.y));
                cv.z = __uint_as_float(f2tf(v.z)); cv.w = __uint_as_float(f2tf(v.w));
                *(float4*)&Hs[b * HSTR + k4 * 4] = cv;
            }
        }
        __syncthreads();

        // tf32 mma over K=512 (64 k8-steps)
        float c0[4] = {0.f, 0.f, 0.f, 0.f};
        float c1[4] = {0.f, 0.f, 0.f, 0.f};
        {
            const float* Ha = Hs + (m0 + gp) * HSTR + tg;    // + kk*8 (+4) / +8*HSTR
            const float2* Wa = Wp2 + (size_t)(nhalf * 2) * 32 + lane;  // + kk*128 (+32 for nt+1)
#pragma unroll
            for (int kk = 0; kk < 64; ++kk) {
                unsigned a[4];
                a[0] = fu(Ha[kk * 8]);
                a[1] = fu(Ha[kk * 8 + 8 * HSTR]);
                a[2] = fu(Ha[kk * 8 + 4]);
                a[3] = fu(Ha[kk * 8 + 8 * HSTR + 4]);
                float2 b0f = Wa[kk * 128];
                float2 b1f = Wa[kk * 128 + 32];
                unsigned b0[2] = { fu(b0f.x), fu(b0f.y) };
                unsigned b1[2] = { fu(b1f.x), fu(b1f.y) };
                mma_tf32(c0, a, b0);
                mma_tf32(c1, a, b1);
            }
        }
        // Write pre-activations to Ps (fragment layout -> [b][c])
        {
            const int r  = m0 + gp;
            const int cA = (nhalf * 2) * 8 + 2 * tg;
            const int cB = (nhalf * 2 + 1) * 8 + 2 * tg;
            *(float2*)&Ps[r * PSTR + cA]       = make_float2(c0[0], c0[1]);
            *(float2*)&Ps[(r + 8) * PSTR + cA] = make_float2(c0[2], c0[3]);
            *(float2*)&Ps[r * PSTR + cB]       = make_float2(c1[0], c1[1]);
            *(float2*)&Ps[(r + 8) * PSTR + cB] = make_float2(c1[2], c1[3]);
        }
        __syncthreads();

        // Pointwise gate update for this block's (b, u) slice (fp32)
        const float* __restrict__ gbase = g_gates + ((size_t)d * SQ + t) * (BB * G4);
        float* __restrict__ hdst = &g_h[buf ^ 1][d][0][0];
#pragma unroll
        for (int e2 = 0; e2 < 2; ++e2) {
            const int e  = tid + e2 * 256;     // 0..511
            const int b  = e >> 3;
            const int uu = e & 7;
            const int u  = u0 + uu;
            const float pi = Ps[b * PSTR + uu]      + gbase[(size_t)b * G4 + u];
            const float pf = Ps[b * PSTR + 8 + uu]  + gbase[(size_t)b * G4 + 512 + u];
            const float pg = Ps[b * PSTR + 16 + uu] + gbase[(size_t)b * G4 + 1024 + u];
            const float po = Ps[b * PSTR + 24 + uu] + gbase[(size_t)b * G4 + 1536 + u];
            const float cprev = g_c[d][b][u];
            const float cn = sigm(pf) * cprev + sigm(pi) * tanhf(pg);
            const float hn = sigm(po) * tanhf(cn);
            g_c[d][b][u] = cn;
            hdst[b * 512 + u] = hn;
            g_x1[((size_t)t * BB + b) * 1024 + d * 512 + u] = hn;
        }
        grid_barrier(nblk);
    }
}

// ---------------------------------------------------------------------------
// Final FC on last time step
// ---------------------------------------------------------------------------
__global__ void fc_kernel(const float* __restrict__ fc_w, const float* __restrict__ fc_b,
                          float* __restrict__ out)
{
    const int b    = blockIdx.x;
    const int w    = threadIdx.x >> 5;
    const int lane = threadIdx.x & 31;
    const float* __restrict__ x  = g_x1 + ((size_t)(SQ - 1) * BB + b) * 1024;
    const float* __restrict__ wr = fc_w + (size_t)w * 1024;
    float sum = 0.0f;
    for (int k = lane; k < 1024; k += 32) sum = fmaf(x[k], wr[k], sum);
#pragma unroll
    for (int o = 16; o; o >>= 1) sum += __shfl_down_sync(0xffffffffu, sum, o);
    if (lane == 0) out[b * 8 + w] = sum + fc_b[w];
}

// ---------------------------------------------------------------------------
// Launch
// ---------------------------------------------------------------------------
extern "C" void kernel_launch(void* const* d_in, const int* in_sizes, int n_in,
                              void* d_out, int out_size)
{
    const float* input_seq = (const float*)d_in[0];
    const float* h0        = (const float*)d_in[1];
    const float* c0        = (const float*)d_in[2];
    const float* w_ih_0f   = (const float*)d_in[3];
    const float* w_hh_0f   = (const float*)d_in[4];
    const float* b_0f      = (const float*)d_in[5];
    const float* w_ih_0b   = (const float*)d_in[6];
    const float* w_hh_0b   = (const float*)d_in[7];
    const float* b_0b      = (const float*)d_in[8];
    const float* w_ih_1f   = (const float*)d_in[9];
    const float* w_hh_1f   = (const float*)d_in[10];
    const float* b_1f      = (const float*)d_in[11];
    const float* w_ih_1b   = (const float*)d_in[12];
    const float* w_hh_1b   = (const float*)d_in[13];
    const float* b_1b      = (const float*)d_in[14];
    const float* fc_w      = (const float*)d_in[15];
    const float* fc_b      = (const float*)d_in[16];
    (void)in_sizes; (void)n_in; (void)out_size;

    cudaFuncSetAttribute(lstm_rec_tc, cudaFuncAttributeMaxDynamicSharedMemorySize, REC_SMEM);

    dim3 ggrid(16, 256, 2);   // 2048/128 cols, 32768/128 rows, 2 dirs

    // Layer 0
    init_state<<<64, 1024>>>(h0, c0, 0);
    gemm_tc<<<ggrid, 256>>>(input_seq, w_ih_0f, b_0f, w_ih_0b, b_0b, 256, 0);
    lstm_rec_tc<<<128, 256, REC_SMEM>>>(w_hh_0f, w_hh_0b);

    // Layer 1 (input = g_x1 from layer 0)
    init_state<<<64, 1024>>>(h0, c0, 1);
    gemm_tc<<<ggrid, 256>>>(nullptr, w_ih_1f, b_1f, w_ih_1b, b_1b, 1024, 1);
    lstm_rec_tc<<<128, 256, REC_SMEM>>>(w_hh_1f, w_hh_1b);

    // FC on last time step
    fc_kernel<<<64, 256>>>(fc_w, fc_b, (float*)d_out);
}

// round 12
// speedup vs baseline: 2.6069x; 1.1958x over previous
#include <cuda_runtime.h>
#include <math.h>

// Problem dims
#define SQ  512
#define BB  64
#define HH  512
#define G4  2048

// ---------------------------------------------------------------------------
// Device scratch (allocation-free rule: __device__ globals)
// ---------------------------------------------------------------------------
__device__ float g_gates[2u * SQ * BB * G4];          // x@Wih^T + b, per dir (fp32)
__device__ float g_x1[(size_t)SQ * BB * 1024];        // layer output, tf32-rounded bits
__device__ float g_h[2][2][BB][HH];                   // double-buffered h (tf32-rounded)
__device__ float g_c[2][BB][HH];                      // c state (fp32 exact, block-private)
__device__ float g_wtf[2][2][2048 * 1024];            // W_ih tf32 bits [layer][dir][j*K+k]
__device__ float g_xin[(size_t)SQ * BB * 256];        // input_seq transposed+tf32 [(t*64+b)*256+k]
__device__ unsigned g_bar_count = 0;
__device__ unsigned g_bar_gen   = 0;

// ---------------------------------------------------------------------------
// Helpers
// ---------------------------------------------------------------------------
__device__ __forceinline__ unsigned f2tf(float x) {
    unsigned u; asm("cvt.rna.tf32.f32 %0, %1;" : "=r"(u) : "f"(x)); return u;
}
__device__ __forceinline__ unsigned fu(float x) { return __float_as_uint(x); }

__device__ __forceinline__ void mma_tf32(float* c, const unsigned* a, const unsigned* b) {
    asm("mma.sync.aligned.m16n8k8.row.col.f32.tf32.tf32.f32 "
        "{%0,%1,%2,%3}, {%4,%5,%6,%7}, {%8,%9}, {%0,%1,%2,%3};"
        : "+f"(c[0]), "+f"(c[1]), "+f"(c[2]), "+f"(c[3])
        : "r"(a[0]), "r"(a[1]), "r"(a[2]), "r"(a[3]), "r"(b[0]), "r"(b[1]));
}

__device__ __forceinline__ unsigned s2u(const void* p) {
    unsigned a;
    asm("{ .reg .u64 t; cvta.to.shared.u64 t, %1; cvt.u32.u64 %0, t; }" : "=r"(a) : "l"(p));
    return a;
}
// cp.async.cg: global -> smem, L1-bypassing (L2 only) => coherent with other SMs' STG
__device__ __forceinline__ void cpa16(unsigned dst, const void* src) {
    asm volatile("cp.async.cg.shared.global [%0], [%1], 16;" :: "r"(dst), "l"(src));
}
__device__ __forceinline__ void cpcommit() { asm volatile("cp.async.commit_group;"); }
template<int N> __device__ __forceinline__ void cpwait() {
    asm volatile("cp.async.wait_group %0;" :: "n"(N));
}

// Fast activations (MUFU-based; rel err ~1e-6, negligible vs tf32's 2e-4)
__device__ __forceinline__ float fsigm(float x)  { return __fdividef(1.0f, 1.0f + __expf(-x)); }
__device__ __forceinline__ float ftanhf(float x) { return 1.0f - __fdividef(2.0f, 1.0f + __expf(2.0f * x)); }

// Sense-reversing grid barrier (128 resident blocks, 1/SM)
__device__ __forceinline__ void grid_barrier(unsigned nblk) {
    __syncthreads();
    if (threadIdx.x == 0) {
        __threadfence();
        unsigned gen = ((volatile unsigned*)&g_bar_gen)[0];
        unsigned prev = atomicAdd(&g_bar_count, 1u);
        if (prev == nblk - 1u) {
            ((volatile unsigned*)&g_bar_count)[0] = 0u;
            __threadfence();
            atomicAdd(&g_bar_gen, 1u);
        } else {
            while (((volatile unsigned*)&g_bar_gen)[0] == gen) { __nanosleep(32); }
        }
        __threadfence();
    }
    __syncthreads();
}

// ---------------------------------------------------------------------------
// One-time converts: W_ih -> tf32 scratch; input_seq -> transposed tf32
// ---------------------------------------------------------------------------
__global__ void conv_w(const float* __restrict__ w, int layer, int dir, int n) {
    int i = blockIdx.x * blockDim.x + threadIdx.x;
    if (i < n) g_wtf[layer][dir][i] = __uint_as_float(f2tf(w[i]));
}
__global__ void conv_x(const float* __restrict__ x) {
    int i = blockIdx.x * blockDim.x + threadIdx.x;   // over 64*512*256, [b][t][k]
    if (i < 64 * 512 * 256) {
        int k = i & 255, t = (i >> 8) & 511, b = i >> 17;
        g_xin[((size_t)t * 64 + b) * 256 + k] = __uint_as_float(f2tf(x[i]));
    }
}

__global__ void init_state(const float* __restrict__ h0, const float* __restrict__ c0, int layer) {
    int i = blockIdx.x * blockDim.x + threadIdx.x;
    const int n = 2 * BB * HH;
    if (i < n) {
        ((float*)g_h)[i] = __uint_as_float(f2tf(h0[(size_t)layer * n + i]));  // h rounded (mma operand)
        ((float*)g_c)[i] = c0[(size_t)layer * n + i];                          // c exact
    }
}

// ---------------------------------------------------------------------------
// Input-projection GEMM, cp.async 2-stage pipeline, tf32 mma (no cvt inside).
// Block 128x128, k-tile 32, 8 warps (warp: 32m x 64n). A,W already tf32 bits.
// ---------------------------------------------------------------------------
#define GST (128 * 36)   // floats per As or Bs tile (pad 36 -> conflict-free frags)

__global__ __launch_bounds__(256, 2) void gemm_tc(
    int layer, int K, const float* __restrict__ bf_, const float* __restrict__ bb_)
{
    const int dir = blockIdx.z;
    const float* __restrict__ A    = layer ? (const float*)g_x1 : (const float*)g_xin;
    const float* __restrict__ W    = g_wtf[layer][dir];
    const float* __restrict__ bias = dir ? bb_ : bf_;
    float* __restrict__ out = g_gates + (size_t)dir * SQ * BB * G4;

    extern __shared__ float sm[];                 // [2 stages][As GST | Bs GST]
    const unsigned uSm = s2u(sm);

    const int tid  = threadIdx.x;
    const int w    = tid >> 5;
    const int lane = tid & 31;
    const int gp   = lane >> 2;
    const int tg   = lane & 3;
    const int mb   = (w >> 1) * 32;
    const int nb   = (w & 1) * 64;
    const int row0 = blockIdx.y * 128;
    const int col0 = blockIdx.x * 128;

    float c0[8][4], c1[8][4];
#pragma unroll
    for (int ni = 0; ni < 8; ++ni)
#pragma unroll
        for (int q = 0; q < 4; ++q) { c0[ni][q] = 0.0f; c1[ni][q] = 0.0f; }

    auto stage = [&](int k0, int s) {
        const unsigned uA = uSm + (unsigned)(s * (2 * GST)) * 4u;
        const unsigned uB = uA + (unsigned)GST * 4u;
#pragma unroll
        for (int l = 0; l < 4; ++l) {
            int f = tid + l * 256, rr = f >> 3, c4 = f & 7;
            cpa16(uA + (unsigned)(rr * 36 + c4 * 4) * 4u, A + (size_t)(row0 + rr) * K + k0 + c4 * 4);
            cpa16(uB + (unsigned)(rr * 36 + c4 * 4) * 4u, W + (size_t)(col0 + rr) * K + k0 + c4 * 4);
        }
    };
    auto compute = [&](int s) {
        const float* As = sm + s * (2 * GST);
        const float* Bs = As + GST;
#pragma unroll
        for (int kk8 = 0; kk8 < 4; ++kk8) {
            const int kb = kk8 * 8;
            unsigned a0[4], a1[4];
            const int m = mb + gp;
            a0[0] = fu(As[m * 36 + kb + tg]);          a0[1] = fu(As[(m + 8) * 36 + kb + tg]);
            a0[2] = fu(As[m * 36 + kb + tg + 4]);      a0[3] = fu(As[(m + 8) * 36 + kb + tg + 4]);
            a1[0] = fu(As[(m + 16) * 36 + kb + tg]);   a1[1] = fu(As[(m + 24) * 36 + kb + tg]);
            a1[2] = fu(As[(m + 16) * 36 + kb + tg + 4]); a1[3] = fu(As[(m + 24) * 36 + kb + tg + 4]);
#pragma unroll
            for (int ni = 0; ni < 8; ++ni) {
                const int n = nb + ni * 8 + gp;
                unsigned b2[2] = { fu(Bs[n * 36 + kb + tg]), fu(Bs[n * 36 + kb + tg + 4]) };
                mma_tf32(c0[ni], a0, b2);
                mma_tf32(c1[ni], a1, b2);
            }
        }
    };

    const int KT = K >> 5;
    stage(0, 0); cpcommit();
    for (int kt = 0; kt < KT; ++kt) {
        if (kt + 1 < KT) { stage((kt + 1) << 5, (kt + 1) & 1); cpcommit(); cpwait<1>(); }
        else             { cpwait<0>(); }
        __syncthreads();
        compute(kt & 1);
        __syncthreads();
    }

    // Epilogue: add bias, write fp32
#pragma unroll
    for (int ni = 0; ni < 8; ++ni) {
        const int col = col0 + nb + ni * 8 + 2 * tg;
        const float bx = bias[col], by = bias[col + 1];
#pragma unroll
        for (int mi = 0; mi < 2; ++mi) {
            float (*cc)[4] = mi ? c1 : c0;
            const int row = row0 + mb + mi * 16 + gp;
            *(float2*)(out + (size_t)row * G4 + col)       = make_float2(cc[ni][0] + bx, cc[ni][1] + by);
            *(float2*)(out + (size_t)(row + 8) * G4 + col) = make_float2(cc[ni][2] + bx, cc[ni][3] + by);
        }
    }
}

// ---------------------------------------------------------------------------
// Persistent recurrent kernel: tf32 mma, cp.async-overlapped H broadcast,
// smem-prefetched gates, fast activations. 128 blocks (dir = blk>>6, 8 units).
// ---------------------------------------------------------------------------
#define HSTR 516
#define PSTR 34
#define REC_SMEM ((64*HSTR + 64*4*32*2 + 64*PSTR + 64*32) * 4)

__global__ __launch_bounds__(256, 1) void lstm_rec_tc(
    const float* __restrict__ whh_f, const float* __restrict__ whh_b)
{
    extern __shared__ float sm[];
    float* Hs  = sm;                           // [64][516] tf32 h bits
    float* Wpf = sm + 64 * HSTR;               // fragment-packed Whh (float2/lane), 16384 fl
    float* Ps  = Wpf + 64 * 4 * 32 * 2;        // [64][34] fp32 pre-acts
    float* Gs  = Ps + 64 * PSTR;               // [64][32] prefetched gates

    const unsigned uHs = s2u(Hs);
    const unsigned uGs = s2u(Gs);

    const int tid  = threadIdx.x;
    const int w    = tid >> 5;
    const int lane = tid & 31;
    const int gp   = lane >> 2;
    const int tg   = lane & 3;
    const int d    = blockIdx.x >> 6;
    const int u0   = (blockIdx.x & 63) * 8;
    const unsigned nblk = gridDim.x;
    const float* __restrict__ whh = d ? whh_b : whh_f;

    const int m0    = (w >> 1) * 16;
    const int nhalf = (w & 1);

    // Build fragment-packed B once (tf32): Wp[kk][nt][lane] = {W[kk8+tg][nt8+gp], W[kk8+4+tg][...]}
    float2* Wp2 = (float2*)Wpf;
    for (int e = tid; e < 64 * 4 * 32; e += 256) {
        int el = e & 31, nt = (e >> 5) & 3, kk = e >> 7;
        int uu = el >> 2, tgg = el & 3;
        size_t jrow = (size_t)(nt * 512 + u0 + uu) * 512;
        int k = kk * 8 + tgg;
        float2 v;
        v.x = __uint_as_float(f2tf(whh[jrow + k]));
        v.y = __uint_as_float(f2tf(whh[jrow + k + 4]));
        Wp2[e] = v;
    }
    __syncthreads();

    for (int step = 0; step < SQ; ++step) {
        const int t   = d ? (SQ - 1 - step) : step;
        const int buf = step & 1;
        const float* __restrict__ gbase = g_gates + ((size_t)d * SQ + t) * (BB * G4);
        const float* hsrc = &g_h[buf][d][0][0];

        // Issue 4 k-chunk H stages + gates prefetch (cp.async.cg, 4 groups)
        auto stage_chunk = [&](int c) {
#pragma unroll
            for (int l = 0; l < 8; ++l) {
                int f = tid + l * 256, b = f >> 5, q = f & 31;
                cpa16(uHs + (unsigned)(b * HSTR + c * 128 + q * 4) * 4u,
                      hsrc + b * 512 + c * 128 + q * 4);
            }
        };
        stage_chunk(0);
        {   // gates: 32B per (b,gate) segment; 256 segments
            int b = tid >> 2, g = tid & 3;
            const float* gs = gbase + (size_t)b * G4 + g * 512 + u0;
            unsigned dst = uGs + (unsigned)(b * 32 + g * 8) * 4u;
            cpa16(dst, gs); cpa16(dst + 16u, gs + 4);
        }
        cpcommit();
        stage_chunk(1); cpcommit();
        stage_chunk(2); cpcommit();
        stage_chunk(3); cpcommit();

        // tf32 mma over K=512, overlapped with staging in 4 chunks of 16 k8-steps
        float c0[4] = {0.f, 0.f, 0.f, 0.f};
        float c1[4] = {0.f, 0.f, 0.f, 0.f};
        const float*  Ha = Hs + (m0 + gp) * HSTR + tg;
        const float2* Wa = Wp2 + (size_t)(nhalf * 2) * 32 + lane;
        auto mma_chunk = [&](int cb) {
#pragma unroll
            for (int kk = cb * 16; kk < cb * 16 + 16; ++kk) {
                unsigned a[4];
                a[0] = fu(Ha[kk * 8]);
                a[1] = fu(Ha[kk * 8 + 8 * HSTR]);
                a[2] = fu(Ha[kk * 8 + 4]);
                a[3] = fu(Ha[kk * 8 + 8 * HSTR + 4]);
                float2 b0f = Wa[kk * 128];
                float2 b1f = Wa[kk * 128 + 32];
                unsigned b0[2] = { fu(b0f.x), fu(b0f.y) };
                unsigned b1[2] = { fu(b1f.x), fu(b1f.y) };
                mma_tf32(c0, a, b0);
                mma_tf32(c1, a, b1);
            }
        };
        cpwait<3>(); __syncthreads(); mma_chunk(0);
        cpwait<2>(); __syncthreads(); mma_chunk(1);
        cpwait<1>(); __syncthreads(); mma_chunk(2);
        cpwait<0>(); __syncthreads(); mma_chunk(3);

        // Pre-activations -> Ps (fragment layout -> [b][c])
        {
            const int r  = m0 + gp;
            const int cA = (nhalf * 2) * 8 + 2 * tg;
            const int cB = (nhalf * 2 + 1) * 8 + 2 * tg;
            *(float2*)&Ps[r * PSTR + cA]       = make_float2(c0[0], c0[1]);
            *(float2*)&Ps[(r + 8) * PSTR + cA] = make_float2(c0[2], c0[3]);
            *(float2*)&Ps[r * PSTR + cB]       = make_float2(c1[0], c1[1]);
            *(float2*)&Ps[(r + 8) * PSTR + cB] = make_float2(c1[2], c1[3]);
        }
        __syncthreads();

        // Pointwise gate update (fp32 state, fast activations, h rounded to tf32)
        float* __restrict__ hdst = &g_h[buf ^ 1][d][0][0];
#pragma unroll
        for (int e2 = 0; e2 < 2; ++e2) {
            const int e  = tid + e2 * 256;
            const int b  = e >> 3;
            const int uu = e & 7;
            const int u  = u0 + uu;
            const float pi = Ps[b * PSTR + uu]      + Gs[b * 32 + uu];
            const float pf = Ps[b * PSTR + 8 + uu]  + Gs[b * 32 + 8 + uu];
            const float pg = Ps[b * PSTR + 16 + uu] + Gs[b * 32 + 16 + uu];
            const float po = Ps[b * PSTR + 24 + uu] + Gs[b * 32 + 24 + uu];
            const float cprev = g_c[d][b][u];
            const float cn = fsigm(pf) * cprev + fsigm(pi) * ftanhf(pg);
            const float hn = fsigm(po) * ftanhf(cn);
            const float hr = __uint_as_float(f2tf(hn));     // round once, reuse everywhere
            g_c[d][b][u] = cn;
            hdst[b * 512 + u] = hr;
            g_x1[((size_t)t * BB + b) * 1024 + d * 512 + u] = hr;
        }
        grid_barrier(nblk);
    }
}

// ---------------------------------------------------------------------------
// Final FC on last time step
// ---------------------------------------------------------------------------
__global__ void fc_kernel(const float* __restrict__ fc_w, const float* __restrict__ fc_b,
                          float* __restrict__ out)
{
    const int b    = blockIdx.x;
    const int w    = threadIdx.x >> 5;
    const int lane = threadIdx.x & 31;
    const float* __restrict__ x  = g_x1 + ((size_t)(SQ - 1) * BB + b) * 1024;
    const float* __restrict__ wr = fc_w + (size_t)w * 1024;
    float sum = 0.0f;
    for (int k = lane; k < 1024; k += 32) sum = fmaf(x[k], wr[k], sum);
#pragma unroll
    for (int o = 16; o; o >>= 1) sum += __shfl_down_sync(0xffffffffu, sum, o);
    if (lane == 0) out[b * 8 + w] = sum + fc_b[w];
}

// ---------------------------------------------------------------------------
// Launch
// ---------------------------------------------------------------------------
extern "C" void kernel_launch(void* const* d_in, const int* in_sizes, int n_in,
                              void* d_out, int out_size)
{
    const float* input_seq = (const float*)d_in[0];
    const float* h0        = (const float*)d_in[1];
    const float* c0        = (const float*)d_in[2];
    const float* w_ih_0f   = (const float*)d_in[3];
    const float* w_hh_0f   = (const float*)d_in[4];
    const float* b_0f      = (const float*)d_in[5];
    const float* w_ih_0b   = (const float*)d_in[6];
    const float* w_hh_0b   = (const float*)d_in[7];
    const float* b_0b      = (const float*)d_in[8];
    const float* w_ih_1f   = (const float*)d_in[9];
    const float* w_hh_1f   = (const float*)d_in[10];
    const float* b_1f      = (const float*)d_in[11];
    const float* w_ih_1b   = (const float*)d_in[12];
    const float* w_hh_1b   = (const float*)d_in[13];
    const float* b_1b      = (const float*)d_in[14];
    const float* fc_w      = (const float*)d_in[15];
    const float* fc_b      = (const float*)d_in[16];
    (void)in_sizes; (void)n_in; (void)out_size;

    const int GEMM_SMEM = 2 * 2 * GST * 4;   // 73,728 B
    cudaFuncSetAttribute(gemm_tc,     cudaFuncAttributeMaxDynamicSharedMemorySize, GEMM_SMEM);
    cudaFuncSetAttribute(lstm_rec_tc, cudaFuncAttributeMaxDynamicSharedMemorySize, REC_SMEM);

    // One-time tf32 conversions
    conv_w<<<(2048 * 256  + 255) / 256, 256>>>(w_ih_0f, 0, 0, 2048 * 256);
    conv_w<<<(2048 * 256  + 255) / 256, 256>>>(w_ih_0b, 0, 1, 2048 * 256);
    conv_w<<<(2048 * 1024 + 255) / 256, 256>>>(w_ih_1f, 1, 0, 2048 * 1024);
    conv_w<<<(2048 * 1024 + 255) / 256, 256>>>(w_ih_1b, 1, 1, 2048 * 1024);
    conv_x<<<(64 * 512 * 256 + 255) / 256, 256>>>(input_seq);

    dim3 ggrid(16, 256, 2);

    // Layer 0
    init_state<<<64, 1024>>>(h0, c0, 0);
    gemm_tc<<<ggrid, 256, GEMM_SMEM>>>(0, 256, b_0f, b_0b);
    lstm_rec_tc<<<128, 256, REC_SMEM>>>(w_hh_0f, w_hh_0b);

    // Layer 1
    init_state<<<64, 1024>>>(h0, c0, 1);
    gemm_tc<<<ggrid, 256, GEMM_SMEM>>>(1, 1024, b_1f, b_1b);
    lstm_rec_tc<<<128, 256, REC_SMEM>>>(w_hh_1f, w_hh_1b);

    // FC on last time step
    fc_kernel<<<64, 256>>>(fc_w, fc_b, (float*)d_out);
}